// round 14
// baseline (speedup 1.0000x reference)
#include <cuda_runtime.h>

// Grid (56, 2, 2): (n_src, o, h).  h = m-half: output cols h*28 .. h*28+27.
// y[o*16+k, n_out, h*28+m] = sum_{i<64, j<3} xs[i][m+j] * W[i,k,j]
// Local xs row (stride 32): xs[i][d] = padded_rolled_x[i][h*28 + d], d in [0,30).
// Global padded coord u: u=0 pad, u=1..56 data with u = 1+((w+1)%56), u=57 pad.
// n_out = (n_src+1)%56 folded into store.
//
// 512 threads = 8 slices x 64.  slice = tid>>6 covers i in [slice*8,+8).
// t64: k = t&15, g = t>>4 in [0,4); m0 = g<3 ? g*8 : 20 (g=3 overlaps g=2 by
// 4 cols; duplicate stores are bitwise identical -> deterministic).
// All slices spill 8 partials (stride 12); 128 threads reduce float4 x 8 slices.

__global__ __launch_bounds__(512, 2)
void shiftconv_kernel(const float* __restrict__ x,
                      const float* __restrict__ Wg,
                      float* __restrict__ y)
{
    __shared__ float xs[64 * 32];          //  8192 B
    __shared__ float Ws[64 * 48];          // 12288 B
    __shared__ float ps[8 * 64 * 12];      // 24576 B   (total 45056 B)

    const int n_src = blockIdx.x;          // 0..55
    const int o     = blockIdx.y;          // 0..1
    const int h     = blockIdx.z;          // 0..1
    const int tid   = threadIdx.x;         // 0..511

    // ---- issue x LDG first: one quad per thread, only the needed window ----
    // h=0 needs w in [0,27] + {55}  -> quads {0..6, 13}
    // h=1 needs w in [26,54]        -> quads {6..13}
    const int xi = tid >> 3;               // row i, 0..63
    const int qi = tid & 7;                // 0..7
    const int q  = h ? (qi + 6) : (qi < 7 ? qi : 13);
    const int w0 = q * 4;
    const float* xbase = x + (o * 64) * 3136 + n_src * 56;
    const float4 v = *(const float4*)(xbase + xi * 3136 + w0);

    // ---- stage W while the LDG is in flight ----
    #pragma unroll
    for (int idx = tid; idx < 64 * 48; idx += 512)
        Ws[idx] = Wg[idx];

    // ---- zero the single pad column in this window ----
    // h=0: d=0 (u=0); h=1: d=29 (u=57)
    if (tid < 64)
        xs[tid * 32 + (h ? 29 : 0)] = 0.0f;

    // ---- scatter quad into xs with roll folded in; filter to window ----
    {
        const int lo = h * 28;
        float* row = &xs[xi * 32];
        const float e[4] = {v.x, v.y, v.z, v.w};
        #pragma unroll
        for (int t = 0; t < 4; t++) {
            int u = w0 + t + 2; if (u > 56) u -= 56;   // 1+((w+1)%56)
            const int d = u - lo;
            if (d >= 0 && d < 30) row[d] = e[t];
        }
    }
    __syncthreads();

    // ---- compute ----
    const int slice = tid >> 6;            // 0..7
    const int t64   = tid & 63;
    const int k     = t64 & 15;
    const int g     = t64 >> 4;            // 0..3
    const int m0    = (g < 3) ? g * 8 : 20;
    const int i0    = slice * 8;

    float acc[8];
    #pragma unroll
    for (int t = 0; t < 8; t++) acc[t] = 0.0f;

    #pragma unroll
    for (int ii = 0; ii < 8; ii++) {
        const int i = i0 + ii;
        const float* wrow = &Ws[i * 48 + k * 3];
        const float w0v = wrow[0];
        const float w1v = wrow[1];
        const float w2v = wrow[2];

        const float* xr = xs + i * 32 + m0;          // 16B aligned (m0 % 4 == 0)
        const float4 a = *(const float4*)(xr);
        const float4 b = *(const float4*)(xr + 4);
        const float2 c = *(const float2*)(xr + 8);
        const float xv[10] = {a.x, a.y, a.z, a.w, b.x, b.y, b.z, b.w, c.x, c.y};

        #pragma unroll
        for (int t = 0; t < 8; t++)
            acc[t] = fmaf(w2v, xv[t + 2],
                     fmaf(w1v, xv[t + 1],
                     fmaf(w0v, xv[t], acc[t])));
    }

    // ---- spill: ps[slice][t64][0..7], stride 12 (16B aligned) ----
    {
        float* p = &ps[(slice * 64 + t64) * 12];
        *(float4*)(p)     = make_float4(acc[0], acc[1], acc[2], acc[3]);
        *(float4*)(p + 4) = make_float4(acc[4], acc[5], acc[6], acc[7]);
    }
    __syncthreads();

    // ---- parallel reduce: 128 threads, one float4 across 8 slices ----
    if (tid < 128) {
        const int a_idx = tid >> 1;                  // 0..63 == t64
        const int hf    = tid & 1;
        const float* base = &ps[a_idx * 12 + hf * 4];

        float4 s = *(const float4*)(base);
        #pragma unroll
        for (int sl = 1; sl < 8; sl++) {
            const float4 t = *(const float4*)(base + sl * 768);
            s.x += t.x; s.y += t.y; s.z += t.z; s.w += t.w;
        }

        const int kk = a_idx & 15;
        const int gg = a_idx >> 4;
        const int mm = ((gg < 3) ? gg * 8 : 20) + hf * 4;
        int n_out = n_src + 1;
        if (n_out == 56) n_out = 0;
        float* yp = y + (o * 16 + kk) * 3136 + n_out * 56 + h * 28 + mm;
        *(float4*)yp = s;
    }
}

extern "C" void kernel_launch(void* const* d_in, const int* in_sizes, int n_in,
                              void* d_out, int out_size)
{
    const float* x  = (const float*)d_in[0];   // (1,128,56,56) = 401408
    const float* Wg = (const float*)d_in[1];   // (64,16,3)     = 3072
    float* y = (float*)d_out;                  // (1,32,56,56)  = 100352

    dim3 grid(56, 2, 2);
    shiftconv_kernel<<<grid, 512>>>(x, Wg, y);
}